// round 15
// baseline (speedup 1.0000x reference)
#include <cuda_runtime.h>
#include <math.h>

// ChebyshevDescriptor — 8 threads per atom, single kernel, batched gathers,
// wrap-free replicated shared table + fully-unrolled pair loop.
// N=20000, K=24, out [N,52] = [rad_un17 | rad_w17 | ang_un9 | ang_w9].
//
// R14 deltas vs R13 (pass 2 only):
//  * shared u-table holds k=0..34 (j<=10 replicated at j+24) so partner
//    index s+r+8m (max 34) needs NO modular wrap -> per-pair IADD/ISETP/SEL
//    eliminated.
//  * r=1..11 loop fully unrolled: partner address = pb[r+8m] with r,m
//    compile-time -> LDS.128 with immediate offsets, zero per-pair index
//    ALU, zero loop control, better load pipelining.
// Gather/radial/reductions/stores identical to R13 (measured-best).

#define N_ATOMS 20000
#define KNBR    24
#define RAD_CUT 8.0f
#define ANG_CUT 6.5f
#define MIN_CUT 0.55f
#define BT      64
#define APB     8            // atoms per block
#define SSTR    37           // float4 stride per atom row (35 used + pad)

__global__ __launch_bounds__(BT, 17)
void cheb_kernel(const float* __restrict__ pos,
                 const int* __restrict__ spec,
                 const int* __restrict__ nbr,
                 float* __restrict__ out) {
    __shared__ float4 s_u4[APB * SSTR];   // 4.7 KB

    const int t = threadIdx.x;
    const int s = t & 7;                  // subthread within octet
    const int a = t >> 3;                 // atom within block
    const int atom = blockIdx.x * APB + a;    // 2500 * 8 == 20000 exactly

    // ---------------- batched gather: indices, then all data loads ----------------
    int nj[3];
    #pragma unroll
    for (int m = 0; m < 3; m++)
        nj[m] = nbr[atom * KNBR + s + 8 * m];

    const float px = pos[3 * atom + 0];
    const float py = pos[3 * atom + 1];
    const float pz = pos[3 * atom + 2];

    float qx[3], qy[3], qz[3];
    int sp[3];
    #pragma unroll
    for (int m = 0; m < 3; m++) {
        qx[m] = pos[3 * nj[m] + 0];
        qy[m] = pos[3 * nj[m] + 1];
        qz[m] = pos[3 * nj[m] + 2];
        sp[m] = spec[nj[m]];
    }

    // ---------------- pass 1: radial partials (load-free compute) ----------------
    float ru[17], rw[17];
    #pragma unroll
    for (int q = 0; q < 17; q++) { ru[q] = 0.0f; rw[q] = 0.0f; }

    float4 myu[3];

    #pragma unroll
    for (int m = 0; m < 3; m++) {
        const int j = s + 8 * m;
        const float dx = qx[m] - px;
        const float dy = qy[m] - py;
        const float dz = qz[m] - pz;
        const float sj = sp[m] ? 1.0f : -1.0f;       // TYPESPIN = [-1, 1]
        const float d2 = dx * dx + dy * dy + dz * dz;
        const float inv = rsqrtf(fmaxf(d2, 1e-18f)); // guard: self-neighbor d=0
        const float d = d2 * inv;

        const bool mr = (d <= RAD_CUT) && (d > MIN_CUT);
        const float fc = 0.5f * (__cosf(d * (3.14159265358979f / RAD_CUT)) + 1.0f);
        const float wr  = mr ? fc : 0.0f;
        const float wrs = wr * sj;
        const float x = mr ? (2.0f * (d - MIN_CUT) * (1.0f / (RAD_CUT - MIN_CUT)) - 1.0f)
                           : 0.0f;   // weight 0 when masked; x=0 keeps T bounded

        const bool ma = (d <= ANG_CUT) && (d > MIN_CUT);
        const float fca = 0.5f * (__cosf(d * (3.14159265358979f / ANG_CUT)) + 1.0f);
        const float wa = ma ? fca : 0.0f;

        const float4 u = make_float4(dx * inv, dy * inv, dz * inv, wa * sj);
        myu[m] = u;
        s_u4[a * SSTR + j] = u;
        if (j <= 10) s_u4[a * SSTR + j + 24] = u;   // replica: wrap-free reads

        ru[0] += wr;        rw[0] += wrs;
        ru[1] += wr * x;    rw[1] += wrs * x;
        const float x2 = x + x;
        float Tmm = 1.0f, Tm = x;
        #pragma unroll
        for (int q = 2; q < 17; q++) {
            const float T = x2 * Tm - Tmm;
            ru[q] += wr * T;
            rw[q] += wrs * T;
            Tmm = Tm; Tm = T;
        }
    }

    // octet-reduce radial (lanes of an atom differ in bits 0..2)
    #pragma unroll
    for (int q = 0; q < 17; q++) {
        ru[q] += __shfl_xor_sync(0xffffffffu, ru[q], 1);
        ru[q] += __shfl_xor_sync(0xffffffffu, ru[q], 2);
        ru[q] += __shfl_xor_sync(0xffffffffu, ru[q], 4);
        rw[q] += __shfl_xor_sync(0xffffffffu, rw[q], 1);
        rw[q] += __shfl_xor_sync(0xffffffffu, rw[q], 2);
        rw[q] += __shfl_xor_sync(0xffffffffu, rw[q], 4);
    }

    float* o = out + (size_t)atom * 52;   // 208B = 16*13 -> 16B-aligned
    if (s == 0) {
        ((float4*)o)[0] = make_float4(ru[0],  ru[1],  ru[2],  ru[3]);
        ((float4*)o)[1] = make_float4(ru[4],  ru[5],  ru[6],  ru[7]);
        ((float4*)o)[2] = make_float4(ru[8],  ru[9],  ru[10], ru[11]);
        ((float4*)o)[3] = make_float4(ru[12], ru[13], ru[14], ru[15]);
        ((float4*)o)[4] = make_float4(ru[16], rw[0],  rw[1],  rw[2]);
        ((float4*)o)[5] = make_float4(rw[3],  rw[4],  rw[5],  rw[6]);
        ((float4*)o)[6] = make_float4(rw[7],  rw[8],  rw[9],  rw[10]);
        ((float4*)o)[7] = make_float4(rw[11], rw[12], rw[13], rw[14]);
        ((float2*)o)[16] = make_float2(rw[15], rw[16]);   // out[32..33]
    }

    __syncwarp();   // staging (incl. replicas) visible: octet is intra-warp

    // ---------------- pass 2: angular, wrap-free, fully unrolled ----------------
    float aU[9], aW[9];
    #pragma unroll
    for (int q = 0; q < 9; q++) { aU[q] = 0.0f; aW[q] = 0.0f; }

    const float4* pb = &s_u4[a * SSTR + s];   // partner = pb[r + 8m], immediate offsets

    #pragma unroll
    for (int r = 1; r <= 11; r++) {
        #pragma unroll
        for (int m = 0; m < 3; m++) {
            const float4 av = myu[m];
            const float4 b = pb[r + 8 * m];   // max index 11+16+s(<=7) = 34 ✓

            const float wsp = av.w * b.w;     // (wa_j sj)(wa_k sk)
            const float wp  = fabsf(wsp);     // wa_j wa_k
            const float ct = av.x * b.x + av.y * b.y + av.z * b.z;   // |ct|<=1+ulp

            aU[0] += wp;        aW[0] += wsp;
            aU[1] += wp * ct;   aW[1] += wsp * ct;
            const float c2 = ct + ct;
            float Tmm = 1.0f, Tm = ct;
            #pragma unroll
            for (int q = 2; q < 9; q++) {
                const float T = c2 * Tm - Tmm;
                aU[q] += wp * T;
                aW[q] += wsp * T;
                Tmm = Tm; Tm = T;
            }
        }
    }
    {   // r = 12: owned j = s+8m < 12  ->  m <= 1 for s < 4, m == 0 for s >= 4
        const int mmax = (s < 4) ? 2 : 1;
        #pragma unroll 1
        for (int m = 0; m < mmax; m++) {
            const float4 av = myu[m];
            const float4 b = pb[12 + 8 * m];  // max index 12+8+7 = 27 ✓

            const float wsp = av.w * b.w;
            const float wp  = fabsf(wsp);
            const float ct = av.x * b.x + av.y * b.y + av.z * b.z;

            aU[0] += wp;        aW[0] += wsp;
            aU[1] += wp * ct;   aW[1] += wsp * ct;
            const float c2 = ct + ct;
            float Tmm = 1.0f, Tm = ct;
            #pragma unroll
            for (int q = 2; q < 9; q++) {
                const float T = c2 * Tm - Tmm;
                aU[q] += wp * T;
                aW[q] += wsp * T;
                Tmm = Tm; Tm = T;
            }
        }
    }

    // octet-reduce angular
    #pragma unroll
    for (int q = 0; q < 9; q++) {
        aU[q] += __shfl_xor_sync(0xffffffffu, aU[q], 1);
        aU[q] += __shfl_xor_sync(0xffffffffu, aU[q], 2);
        aU[q] += __shfl_xor_sync(0xffffffffu, aU[q], 4);
        aW[q] += __shfl_xor_sync(0xffffffffu, aW[q], 1);
        aW[q] += __shfl_xor_sync(0xffffffffu, aW[q], 2);
        aW[q] += __shfl_xor_sync(0xffffffffu, aW[q], 4);
    }

    if (s == 0) {   // out[34..51], 8B-aligned base -> float2 stores
        float2* o2 = (float2*)(o + 34);
        o2[0] = make_float2(aU[0], aU[1]);
        o2[1] = make_float2(aU[2], aU[3]);
        o2[2] = make_float2(aU[4], aU[5]);
        o2[3] = make_float2(aU[6], aU[7]);
        o2[4] = make_float2(aU[8], aW[0]);
        o2[5] = make_float2(aW[1], aW[2]);
        o2[6] = make_float2(aW[3], aW[4]);
        o2[7] = make_float2(aW[5], aW[6]);
        o2[8] = make_float2(aW[7], aW[8]);
    }
}

extern "C" void kernel_launch(void* const* d_in, const int* in_sizes, int n_in,
                              void* d_out, int out_size) {
    const float* positions  = (const float*)d_in[0];
    const int* species_idx  = (const int*)d_in[1];
    const int* neighbor_idx = (const int*)d_in[2];
    float* out = (float*)d_out;

    cheb_kernel<<<N_ATOMS / APB, BT>>>(positions, species_idx, neighbor_idx, out);
}

// round 17
// speedup vs baseline: 1.0092x; 1.0092x over previous
#include <cuda_runtime.h>
#include <math.h>

// ChebyshevDescriptor — 8 threads per atom, single kernel, batched gathers.
// N=20000, K=24, out [N,52] = [rad_un17 | rad_w17 | ang_un9 | ang_w9].
//
// R16 = R15 resubmission (prior round died in container acquisition — same
// infra failure mode as R5/R6, which R11 proved content-independent) with
// ONE fix found in re-audit: replica store condition was j<=10 but the
// masked (r=12, m=2) load reads slot 35 = replica of j=11 -> uninitialized
// shared; garbage*0 could be NaN. Now j<=11.
//
// R15 deltas vs R13 (best fused body):
//  * replicated shared table (j<=11 mirrored at j+24) -> partner index
//    r+8m+s needs no modular wrap; r loop stays ROLLED (R14: full unroll
//    trades the ALU win for I$/scheduling stalls).
//  * r=1..12 uniform loop with per-m duplicate masks (m=0 always; m=1 iff
//    r<12||s<4; m=2 iff r<12).
//  * launch_bounds(64,18).

#define N_ATOMS 20000
#define KNBR    24
#define RAD_CUT 8.0f
#define ANG_CUT 6.5f
#define MIN_CUT 0.55f
#define BT      64
#define APB     8            // atoms per block
#define SSTR    37           // float4 stride per atom row (36 used + pad)

__global__ __launch_bounds__(BT, 18)
void cheb_kernel(const float* __restrict__ pos,
                 const int* __restrict__ spec,
                 const int* __restrict__ nbr,
                 float* __restrict__ out) {
    __shared__ float4 s_u4[APB * SSTR];   // 4.7 KB

    const int t = threadIdx.x;
    const int s = t & 7;                  // subthread within octet
    const int a = t >> 3;                 // atom within block
    const int atom = blockIdx.x * APB + a;    // 2500 * 8 == 20000 exactly

    // ---------------- batched gather: indices, then all data loads ----------------
    int nj[3];
    #pragma unroll
    for (int m = 0; m < 3; m++)
        nj[m] = nbr[atom * KNBR + s + 8 * m];

    const float px = pos[3 * atom + 0];
    const float py = pos[3 * atom + 1];
    const float pz = pos[3 * atom + 2];

    float qx[3], qy[3], qz[3];
    int sp[3];
    #pragma unroll
    for (int m = 0; m < 3; m++) {
        qx[m] = pos[3 * nj[m] + 0];
        qy[m] = pos[3 * nj[m] + 1];
        qz[m] = pos[3 * nj[m] + 2];
        sp[m] = spec[nj[m]];
    }

    // ---------------- pass 1: radial partials (load-free compute) ----------------
    float ru[17], rw[17];
    #pragma unroll
    for (int q = 0; q < 17; q++) { ru[q] = 0.0f; rw[q] = 0.0f; }

    float4 myu[3];

    #pragma unroll
    for (int m = 0; m < 3; m++) {
        const int j = s + 8 * m;
        const float dx = qx[m] - px;
        const float dy = qy[m] - py;
        const float dz = qz[m] - pz;
        const float sj = sp[m] ? 1.0f : -1.0f;       // TYPESPIN = [-1, 1]
        const float d2 = dx * dx + dy * dy + dz * dz;
        const float inv = rsqrtf(fmaxf(d2, 1e-18f)); // guard: self-neighbor d=0
        const float d = d2 * inv;

        const bool mr = (d <= RAD_CUT) && (d > MIN_CUT);
        const float fc = 0.5f * (__cosf(d * (3.14159265358979f / RAD_CUT)) + 1.0f);
        const float wr  = mr ? fc : 0.0f;
        const float wrs = wr * sj;
        const float x = mr ? (2.0f * (d - MIN_CUT) * (1.0f / (RAD_CUT - MIN_CUT)) - 1.0f)
                           : 0.0f;   // weight 0 when masked; x=0 keeps T bounded

        const bool ma = (d <= ANG_CUT) && (d > MIN_CUT);
        const float fca = 0.5f * (__cosf(d * (3.14159265358979f / ANG_CUT)) + 1.0f);
        const float wa = ma ? fca : 0.0f;

        const float4 u = make_float4(dx * inv, dy * inv, dz * inv, wa * sj);
        myu[m] = u;
        s_u4[a * SSTR + j] = u;
        if (j <= 11) s_u4[a * SSTR + j + 24] = u;   // replicas for wrap-free reads
                                                    // (incl. j=11: slot 35 is READ
                                                    //  by the masked r=12,m=2 pair)

        ru[0] += wr;        rw[0] += wrs;
        ru[1] += wr * x;    rw[1] += wrs * x;
        const float x2 = x + x;
        float Tmm = 1.0f, Tm = x;
        #pragma unroll
        for (int q = 2; q < 17; q++) {
            const float T = x2 * Tm - Tmm;
            ru[q] += wr * T;
            rw[q] += wrs * T;
            Tmm = Tm; Tm = T;
        }
    }

    // octet-reduce radial (lanes of an atom differ in bits 0..2)
    #pragma unroll
    for (int q = 0; q < 17; q++) {
        ru[q] += __shfl_xor_sync(0xffffffffu, ru[q], 1);
        ru[q] += __shfl_xor_sync(0xffffffffu, ru[q], 2);
        ru[q] += __shfl_xor_sync(0xffffffffu, ru[q], 4);
        rw[q] += __shfl_xor_sync(0xffffffffu, rw[q], 1);
        rw[q] += __shfl_xor_sync(0xffffffffu, rw[q], 2);
        rw[q] += __shfl_xor_sync(0xffffffffu, rw[q], 4);
    }

    float* o = out + (size_t)atom * 52;   // 208B = 16*13 -> 16B-aligned
    if (s == 0) {
        ((float4*)o)[0] = make_float4(ru[0],  ru[1],  ru[2],  ru[3]);
        ((float4*)o)[1] = make_float4(ru[4],  ru[5],  ru[6],  ru[7]);
        ((float4*)o)[2] = make_float4(ru[8],  ru[9],  ru[10], ru[11]);
        ((float4*)o)[3] = make_float4(ru[12], ru[13], ru[14], ru[15]);
        ((float4*)o)[4] = make_float4(ru[16], rw[0],  rw[1],  rw[2]);
        ((float4*)o)[5] = make_float4(rw[3],  rw[4],  rw[5],  rw[6]);
        ((float4*)o)[6] = make_float4(rw[7],  rw[8],  rw[9],  rw[10]);
        ((float4*)o)[7] = make_float4(rw[11], rw[12], rw[13], rw[14]);
        ((float2*)o)[16] = make_float2(rw[15], rw[16]);   // out[32..33]
    }

    __syncwarp();   // staging (incl. replicas) visible: octet is intra-warp

    // ---------------- pass 2: angular, rolled uniform r=1..12 loop ----------------
    float aU[9], aW[9];
    #pragma unroll
    for (int q = 0; q < 9; q++) { aU[q] = 0.0f; aW[q] = 0.0f; }

    const float4* pb = &s_u4[a * SSTR + s];   // partner = pb[r + 8m], wrap-free

    #pragma unroll 1
    for (int r = 1; r <= 12; r++) {
        // per-m validity masks (uniform tail fold): m=0 always; m=1 iff
        // r<12 or s<4; m=2 iff r<12. Masked pairs are duplicates -> weight 0.
        const bool last = (r == 12);
        const float msk1 = (!last || s < 4) ? 1.0f : 0.0f;
        const float msk2 = last ? 0.0f : 1.0f;
        #pragma unroll
        for (int m = 0; m < 3; m++) {
            const float mm = (m == 0) ? 1.0f : ((m == 1) ? msk1 : msk2);
            const float4 av = myu[m];
            const float4 b = pb[r + 8 * m];   // max index 12+16+7 = 35 < SSTR ✓

            const float wsp = mm * av.w * b.w;   // (wa_j sj)(wa_k sk), 0 if masked
            const float wp  = fabsf(wsp);        // wa_j wa_k
            const float ct = av.x * b.x + av.y * b.y + av.z * b.z;   // |ct|<=1+ulp

            aU[0] += wp;        aW[0] += wsp;
            aU[1] += wp * ct;   aW[1] += wsp * ct;
            const float c2 = ct + ct;
            float Tmm = 1.0f, Tm = ct;
            #pragma unroll
            for (int q = 2; q < 9; q++) {
                const float T = c2 * Tm - Tmm;
                aU[q] += wp * T;
                aW[q] += wsp * T;
                Tmm = Tm; Tm = T;
            }
        }
    }

    // octet-reduce angular
    #pragma unroll
    for (int q = 0; q < 9; q++) {
        aU[q] += __shfl_xor_sync(0xffffffffu, aU[q], 1);
        aU[q] += __shfl_xor_sync(0xffffffffu, aU[q], 2);
        aU[q] += __shfl_xor_sync(0xffffffffu, aU[q], 4);
        aW[q] += __shfl_xor_sync(0xffffffffu, aW[q], 1);
        aW[q] += __shfl_xor_sync(0xffffffffu, aW[q], 2);
        aW[q] += __shfl_xor_sync(0xffffffffu, aW[q], 4);
    }

    if (s == 0) {   // out[34..51], 8B-aligned base -> float2 stores
        float2* o2 = (float2*)(o + 34);
        o2[0] = make_float2(aU[0], aU[1]);
        o2[1] = make_float2(aU[2], aU[3]);
        o2[2] = make_float2(aU[4], aU[5]);
        o2[3] = make_float2(aU[6], aU[7]);
        o2[4] = make_float2(aU[8], aW[0]);
        o2[5] = make_float2(aW[1], aW[2]);
        o2[6] = make_float2(aW[3], aW[4]);
        o2[7] = make_float2(aW[5], aW[6]);
        o2[8] = make_float2(aW[7], aW[8]);
    }
}

extern "C" void kernel_launch(void* const* d_in, const int* in_sizes, int n_in,
                              void* d_out, int out_size) {
    const float* positions  = (const float*)d_in[0];
    const int* species_idx  = (const int*)d_in[1];
    const int* neighbor_idx = (const int*)d_in[2];
    float* out = (float*)d_out;

    cheb_kernel<<<N_ATOMS / APB, BT>>>(positions, species_idx, neighbor_idx, out);
}